// round 9
// baseline (speedup 1.0000x reference)
#include <cuda_runtime.h>
#include <cuda_bf16.h>
#include <cuda_fp16.h>
#include <cstdint>

// Problem constants (fixed shapes from reference)
#define B_  32
#define S_  512
#define H_  768
#define P_  76
#define K_  64
#define E_  768
#define M_  (B_ * P_)     // 2432
#define V_  50257
#define EMB_F4 9649344    // V_*E_/4 float4 count

// ---------------- device scratch (no allocs allowed) ----------------
__device__ __align__(16) float          g_lm[M_ * E_];    // pre-LN dense out
__device__ __align__(16) __nv_bfloat16  g_ahi[M_ * H_];   // gathered A hi
__device__ __align__(16) __nv_bfloat16  g_alo[M_ * H_];   // gathered A lo
__device__ __align__(16) __nv_bfloat16  g_whi[H_ * E_];   // W hi (row-major = mma B)
__device__ __align__(16) __nv_bfloat16  g_wlo[H_ * E_];   // W lo
__device__ __align__(16) __half         g_ehalf[V_ * E_]; // fp16 embedding table
__device__ int g_c64;                                     // cand idx int64?

// ---------------- helpers ----------------
__device__ __forceinline__ uint32_t smem_u32(const void* p) {
    uint32_t a;
    asm("{ .reg .u64 t; cvta.to.shared.u64 t, %1; cvt.u32.u64 %0, t; }"
        : "=r"(a) : "l"(p));
    return a;
}
__device__ __forceinline__ void cp16(uint32_t s, const void* g) {
    asm volatile("cp.async.cg.shared.global [%0], [%1], 16;" :: "r"(s), "l"(g));
}
__device__ __forceinline__ void ldm_x4(uint32_t* r, uint32_t addr) {
    asm volatile("ldmatrix.sync.aligned.m8n8.x4.shared.b16 {%0,%1,%2,%3}, [%4];"
                 : "=r"(r[0]), "=r"(r[1]), "=r"(r[2]), "=r"(r[3]) : "r"(addr));
}
__device__ __forceinline__ void ldm_x4_t(uint32_t* r, uint32_t addr) {
    asm volatile("ldmatrix.sync.aligned.m8n8.x4.trans.shared.b16 {%0,%1,%2,%3}, [%4];"
                 : "=r"(r[0]), "=r"(r[1]), "=r"(r[2]), "=r"(r[3]) : "r"(addr));
}
__device__ __forceinline__ void mma_bf16(float* d, const uint32_t* a,
                                         uint32_t b0, uint32_t b1) {
    asm volatile(
        "mma.sync.aligned.m16n8k16.row.col.f32.bf16.bf16.f32 "
        "{%0,%1,%2,%3}, {%4,%5,%6,%7}, {%8,%9}, {%0,%1,%2,%3};"
        : "+f"(d[0]), "+f"(d[1]), "+f"(d[2]), "+f"(d[3])
        : "r"(a[0]), "r"(a[1]), "r"(a[2]), "r"(a[3]), "r"(b0), "r"(b1));
}

// ---------------------------------------------------------------------------
// Prep (496 blocks):
//  blocks [0,304):   gather 8 seq rows each via masked_positions -> bf16 hi/lo
//  blocks [304,496): split W (3072 elems each) -> bf16 hi/lo
// Index dtype detection: int64 LE nonneg < 2^31 => odd 32-bit words all zero.
// ---------------------------------------------------------------------------
__global__ void __launch_bounds__(256)
prep_kernel(const float* __restrict__ seq, const int* __restrict__ mraw,
            const int* __restrict__ craw, const float* __restrict__ W)
{
    const int blk = blockIdx.x;
    const int tid = threadIdx.x;

    if (blk < 304) {
        __shared__ int nzm;
        if (tid == 0) nzm = 0;
        __syncthreads();
#pragma unroll
        for (int j = 0; j < 2; j++)
            if (mraw[2 * (tid + j * 256) + 1] != 0) atomicOr(&nzm, 1);  // 1024 w <= M_
        __syncthreads();
        const int m64 = (nzm == 0);
#pragma unroll
        for (int j = 0; j < 8; j++) {
            const int m = blk * 8 + j;
            const int pos = m64 ? mraw[2 * m] : mraw[m];
            const int b = m / P_;
            const float* src = seq + (size_t)(b * S_ + pos) * H_;
#pragma unroll
            for (int i = 0; i < 3; i++) {
                float v = src[tid + i * 256];
                __nv_bfloat16 hi = __float2bfloat16(v);
                __nv_bfloat16 lo = __float2bfloat16(v - __bfloat162float(hi));
                g_ahi[(size_t)m * H_ + tid + i * 256] = hi;
                g_alo[(size_t)m * H_ + tid + i * 256] = lo;
            }
        }
    } else {
        const int blk2 = blk - 304;          // 0..191
        const int base = blk2 * 3072;
#pragma unroll
        for (int i = 0; i < 12; i++) {
            int idx = base + i * 256 + tid;  // < 589824
            float v = W[idx];
            __nv_bfloat16 hi = __float2bfloat16(v);
            __nv_bfloat16 lo = __float2bfloat16(v - __bfloat162float(hi));
            g_whi[idx] = hi;
            g_wlo[idx] = lo;
        }
        if (blk2 == 0) {
            __shared__ int nzc;
            if (tid == 0) nzc = 0;
            __syncthreads();
            if (craw[2 * tid + 1] != 0) atomicOr(&nzc, 1);   // 512 w <= M_*K_
            __syncthreads();
            if (tid == 0) g_c64 = (nzc == 0);
        }
    }
}

// ---------------------------------------------------------------------------
// GEMM: bf16 mma.sync m16n8k16, 3-term hi/lo split (fp32-accurate).
// 64x96 tile/CTA, grid 8 x 38 = 304 CTAs -> 2 resident CTAs/SM.
// ALSO converts the fp32 embedding table -> fp16 (g_ehalf), interleaved per
// k-chunk so the DRAM traffic hides under the tensor-pipe shadow and the
// stores pre-warm L2 for the logits kernel.
// ---------------------------------------------------------------------------
#define A_STR 40
#define B_STR 104

__global__ void __launch_bounds__(256)
gemm_mma_kernel(const float* __restrict__ bias, const float4* __restrict__ embf4)
{
    __shared__ __align__(16) __nv_bfloat16 sAhi[2][64][A_STR];
    __shared__ __align__(16) __nv_bfloat16 sAlo[2][64][A_STR];
    __shared__ __align__(16) __nv_bfloat16 sBhi[2][32][B_STR];
    __shared__ __align__(16) __nv_bfloat16 sBlo[2][32][B_STR];

    const int tid  = threadIdx.x;
    const int wid  = tid >> 5;
    const int lane = tid & 31;
    const int row0 = blockIdx.y * 64;
    const int col0 = blockIdx.x * 96;
    const int bid  = blockIdx.y * 8 + blockIdx.x;   // 0..303
    const int wm   = (wid >> 1) * 16;
    const int wn   = (wid & 1) * 48;

    const int ar = tid >> 2, ac = (tid & 3) * 8;
    const int br0 = tid / 12, bc0 = (tid % 12) * 8;
    const int br1 = (tid + 256) / 12, bc1 = ((tid + 256) % 12) * 8;

    float acc[6][4];
#pragma unroll
    for (int i = 0; i < 6; i++)
#pragma unroll
        for (int q = 0; q < 4; q++) acc[i][q] = 0.f;

    auto load_chunk = [&](int c, int buf) {
        const int k0 = c * 32;
        cp16(smem_u32(&sAhi[buf][ar][ac]), g_ahi + (size_t)(row0 + ar) * H_ + k0 + ac);
        cp16(smem_u32(&sAlo[buf][ar][ac]), g_alo + (size_t)(row0 + ar) * H_ + k0 + ac);
        cp16(smem_u32(&sBhi[buf][br0][bc0]), g_whi + (size_t)(k0 + br0) * E_ + col0 + bc0);
        cp16(smem_u32(&sBlo[buf][br0][bc0]), g_wlo + (size_t)(k0 + br0) * E_ + col0 + bc0);
        if (tid < 128) {
            cp16(smem_u32(&sBhi[buf][br1][bc1]), g_whi + (size_t)(k0 + br1) * E_ + col0 + bc1);
            cp16(smem_u32(&sBlo[buf][br1][bc1]), g_wlo + (size_t)(k0 + br1) * E_ + col0 + bc1);
        }
    };

    load_chunk(0, 0);
    asm volatile("cp.async.commit_group;" ::: "memory");

    const int l15 = lane & 15, lh = lane >> 4;

    for (int c = 0; c < 24; ++c) {
        const int buf = c & 1;
        if (c + 1 < 24) {
            load_chunk(c + 1, 1 - buf);
            asm volatile("cp.async.commit_group;" ::: "memory");
            asm volatile("cp.async.wait_group 1;" ::: "memory");
        } else {
            asm volatile("cp.async.wait_group 0;" ::: "memory");
        }
        __syncthreads();

#pragma unroll
        for (int ks = 0; ks < 2; ++ks) {
            uint32_t bh[3][4], bl[3][4];
#pragma unroll
            for (int g = 0; g < 3; ++g) {
                ldm_x4_t(bh[g], smem_u32(&sBhi[buf][ks * 16 + l15][wn + g * 16 + lh * 8]));
                ldm_x4_t(bl[g], smem_u32(&sBlo[buf][ks * 16 + l15][wn + g * 16 + lh * 8]));
            }
            uint32_t ah[4], al[4];
            ldm_x4(ah, smem_u32(&sAhi[buf][wm + l15][ks * 16 + lh * 8]));
            ldm_x4(al, smem_u32(&sAlo[buf][wm + l15][ks * 16 + lh * 8]));
#pragma unroll
            for (int g = 0; g < 3; ++g) {
#pragma unroll
                for (int s = 0; s < 2; ++s) {
                    float* d = acc[g * 2 + s];
                    mma_bf16(d, ah, bh[g][s * 2], bh[g][s * 2 + 1]);
                    mma_bf16(d, ah, bl[g][s * 2], bl[g][s * 2 + 1]);
                    mma_bf16(d, al, bh[g][s * 2], bh[g][s * 2 + 1]);
                }
            }
        }

        // --- interleaved fp32 -> fp16 table conversion slab for this chunk ---
        {
            const long base = (long)(bid * 24 + c) * 1323;
#pragma unroll
            for (int i = 0; i < 6; ++i) {
                const int off = i * 256 + tid;
                const long idx = base + off;
                if (off < 1323 && idx < (long)EMB_F4) {
                    float4 v = embf4[idx];
                    __half2 h01 = __floats2half2_rn(v.x, v.y);
                    __half2 h23 = __floats2half2_rn(v.z, v.w);
                    uint2 st;
                    st.x = *(uint32_t*)&h01;
                    st.y = *(uint32_t*)&h23;
                    *reinterpret_cast<uint2*>(g_ehalf + idx * 4) = st;
                }
            }
        }
        __syncthreads();
    }

    // Epilogue: + bias, fp32 store
    const int lr = lane >> 2, lc2 = (lane & 3) * 2;
#pragma unroll
    for (int nf = 0; nf < 6; ++nf) {
        const int col = col0 + wn + nf * 8 + lc2;
        const float2 bb = *(const float2*)(bias + col);
        const int r0 = row0 + wm + lr;
        float2 v0, v1;
        v0.x = acc[nf][0] + bb.x;  v0.y = acc[nf][1] + bb.y;
        v1.x = acc[nf][2] + bb.x;  v1.y = acc[nf][3] + bb.y;
        *(float2*)(g_lm + (size_t)r0 * E_ + col)       = v0;
        *(float2*)(g_lm + (size_t)(r0 + 8) * E_ + col) = v1;
    }
}

// ---------------------------------------------------------------------------
// Logits: per-(b,p) LayerNorm (fused) + 64 candidate dots against the fp16
// table (half the gather bytes; table is L2-resident after the GEMM's stores).
// One block per row, 8 warps x 8 candidates, pairs for MLP.
// ---------------------------------------------------------------------------
__global__ void __launch_bounds__(256)
logits_kernel(const int*   __restrict__ craw,
              const float* __restrict__ gamma,
              const float* __restrict__ beta,
              float* __restrict__ out)
{
    __shared__ __align__(16) float lm_s[E_];
    __shared__ float red[16];
    __shared__ float mu_s, rinv_s;

    const int bp   = blockIdx.x;
    const int tid  = threadIdx.x;
    const int wid  = tid >> 5;
    const int lane = tid & 31;
    const int c64  = g_c64;

    const float* row = g_lm + (size_t)bp * E_;
    float x0 = row[tid];
    float x1 = row[tid + 256];
    float x2 = row[tid + 512];

    float s  = x0 + x1 + x2;
    float sq = x0 * x0 + x1 * x1 + x2 * x2;
#pragma unroll
    for (int o = 16; o; o >>= 1) {
        s  += __shfl_xor_sync(0xffffffffu, s,  o);
        sq += __shfl_xor_sync(0xffffffffu, sq, o);
    }
    if (lane == 0) { red[wid] = s; red[wid + 8] = sq; }
    __syncthreads();
    if (tid == 0) {
        float S = 0.f, SQ = 0.f;
#pragma unroll
        for (int w = 0; w < 8; w++) { S += red[w]; SQ += red[w + 8]; }
        float mu  = S * (1.0f / E_);
        float var = SQ * (1.0f / E_) - mu * mu;
        mu_s   = mu;
        rinv_s = rsqrtf(var + 1e-12f);
    }
    __syncthreads();
    const float mu = mu_s, rinv = rinv_s;

    lm_s[tid]       = (x0 - mu) * rinv * gamma[tid]       + beta[tid];
    lm_s[tid + 256] = (x1 - mu) * rinv * gamma[tid + 256] + beta[tid + 256];
    lm_s[tid + 512] = (x2 - mu) * rinv * gamma[tid + 512] + beta[tid + 512];
    __syncthreads();

    const float4* lp = (const float4*)lm_s;

#pragma unroll
    for (int kk = 0; kk < 4; kk++) {
        int k  = wid * 8 + kk * 2;
        int i0 = bp * K_ + k;
        int c0 = c64 ? craw[2 * i0]     : craw[i0];
        int c1 = c64 ? craw[2 * i0 + 2] : craw[i0 + 1];
        const uint4* e0 = (const uint4*)(g_ehalf + (size_t)c0 * E_);
        const uint4* e1 = (const uint4*)(g_ehalf + (size_t)c1 * E_);
        float a0 = 0.f, a1 = 0.f;
#pragma unroll
        for (int j = 0; j < 3; j++) {
            uint4 q0 = e0[j * 32 + lane];
            uint4 q1 = e1[j * 32 + lane];
            float4 l0 = lp[j * 64 + lane * 2];
            float4 l1 = lp[j * 64 + lane * 2 + 1];
            float2 f;
            f = __half22float2(*(__half2*)&q0.x); a0 += f.x * l0.x + f.y * l0.y;
            f = __half22float2(*(__half2*)&q0.y); a0 += f.x * l0.z + f.y * l0.w;
            f = __half22float2(*(__half2*)&q0.z); a0 += f.x * l1.x + f.y * l1.y;
            f = __half22float2(*(__half2*)&q0.w); a0 += f.x * l1.z + f.y * l1.w;
            f = __half22float2(*(__half2*)&q1.x); a1 += f.x * l0.x + f.y * l0.y;
            f = __half22float2(*(__half2*)&q1.y); a1 += f.x * l0.z + f.y * l0.w;
            f = __half22float2(*(__half2*)&q1.z); a1 += f.x * l1.x + f.y * l1.y;
            f = __half22float2(*(__half2*)&q1.w); a1 += f.x * l1.z + f.y * l1.w;
        }
#pragma unroll
        for (int o = 16; o; o >>= 1) {
            a0 += __shfl_xor_sync(0xffffffffu, a0, o);
            a1 += __shfl_xor_sync(0xffffffffu, a1, o);
        }
        if (lane == 0) {
            out[i0]     = a0;
            out[i0 + 1] = a1;
        }
    }
}

// ---------------------------------------------------------------------------
extern "C" void kernel_launch(void* const* d_in, const int* in_sizes, int n_in,
                              void* d_out, int out_size)
{
    const float* seq   = (const float*)d_in[0];
    const int*   mraw  = (const int*)d_in[1];
    const int*   craw  = (const int*)d_in[2];
    const float* emb   = (const float*)d_in[3];
    const float* W     = (const float*)d_in[4];
    const float* bias  = (const float*)d_in[5];
    const float* gamma = (const float*)d_in[6];
    const float* beta  = (const float*)d_in[7];
    float*       out   = (float*)d_out;

    prep_kernel<<<496, 256>>>(seq, mraw, craw, W);
    dim3 g1(E_ / 96, M_ / 64);   // 8 x 38 = 304 CTAs
    gemm_mma_kernel<<<g1, 256>>>(bias, (const float4*)emb);
    logits_kernel<<<M_, 256>>>(craw, gamma, beta, out);
}